// round 6
// baseline (speedup 1.0000x reference)
#include <cuda_runtime.h>

// Problem constants (fixed shapes per reference):
//   z: [32,256,64,64] f32 -> flat [131072, 256]
//   codebook: [512, 256], n_i: [512], e_i: [512,256]
#define NR 131072
#define DD 256
#define KK 512
#define NV4 (NR * DD / 4)   // 8388608 float4 elements of z

// Output layout (concatenated reference tuple, all float32):
//   code_ste [33554432], loss [1], encoding [131072],
//   codebook_new [131072], n_new [512], e_new [131072]
#define OFF_LOSS 33554432
#define OFF_ENC  33554433
#define OFF_CB   33685505
#define OFF_N    33816577
#define OFF_E    33817089

#define NSEG 8    // segments per code for balanced EMA partial pass

// -------- device scratch (no allocations allowed) --------
static __device__ int    g_enc[NR];
static __device__ int    g_rowlist[NR];
static __device__ int    g_counts[KK];
static __device__ int    g_offsets[KK];
static __device__ int    g_cursor[KK];
static __device__ float  g_halfnorm[KK];
static __device__ double g_hnd[KK];
static __device__ int    g_fixn;
static __device__ int    g_fixrows[8192];
static __device__ float  g_epart[KK * NSEG * DD];
static __device__ double g_losspart[8192];

// -------- packed f32x2 helpers --------
__device__ __forceinline__ void ffma2(unsigned long long& d, unsigned long long a,
                                      unsigned long long b) {
    asm("fma.rn.f32x2 %0, %1, %2, %0;" : "+l"(d) : "l"(a), "l"(b));
}
__device__ __forceinline__ float2 unpack2(unsigned long long v) {
    float2 p;
    asm("mov.b64 {%0, %1}, %2;" : "=f"(p.x), "=f"(p.y) : "l"(v));
    return p;
}
__device__ __forceinline__ void cp8(unsigned dst, const float* src) {
    asm volatile("cp.async.ca.shared.global [%0], [%1], 8;"
                 :: "r"(dst), "l"((unsigned long long)__cvta_generic_to_global(src)));
}
__device__ __forceinline__ void cp_commit() { asm volatile("cp.async.commit_group;"); }
__device__ __forceinline__ void cp_wait0()  { asm volatile("cp.async.wait_group 0;"); }
__device__ __forceinline__ void lds_v2u64(unsigned long long& a, unsigned long long& b,
                                          unsigned addr) {
    asm("ld.shared.v2.u64 {%0,%1}, [%2];" : "=l"(a), "=l"(b) : "r"(addr));
}

// -------- halfnorm + per-replay state init --------
__global__ void halfnorm_kernel(const float* __restrict__ cb) {
    int k = blockIdx.x;
    float v = cb[k * DD + threadIdx.x];
    double s = (double)v * (double)v;
    #pragma unroll
    for (int o = 16; o > 0; o >>= 1) s += __shfl_xor_sync(0xffffffffu, s, o);
    __shared__ double sm[8];
    if ((threadIdx.x & 31) == 0) sm[threadIdx.x >> 5] = s;
    __syncthreads();
    if (threadIdx.x == 0) {
        double tot = 0.0;
        #pragma unroll
        for (int i = 0; i < 8; i++) tot += sm[i];
        g_hnd[k] = 0.5 * tot;
        g_halfnorm[k] = (float)(0.5 * tot);
        g_counts[k] = 0;                    // per-replay zero (graph replays!)
        if (k == 0) g_fixn = 0;
    }
}

// -------- pad: places argmin at launches #3 and #4 (capture is one of them) ---
__global__ void pad_kernel() {}

// -------- fused GEMM + top-2 argmax over codes --------
// argmin dist == argmax (x.c - 0.5||c||^2). Block: 128 rows x all 512 codes
// (4 chunks of 128). 512 threads; per-thread 8 rows x 4 cols.
// FFMA2 pairs over k, cp.async double-buffered tiles, conflict-free LDS.
// occupancy 2 -> 32 warps/SM to hide sync/prefetch bubbles.
__global__ __launch_bounds__(512, 2) void argmin_kernel(
        const float* __restrict__ z, const float* __restrict__ cb,
        float* __restrict__ enc_f, int row_base) {
    __shared__ float As[2][4][128][4];   // [buf][kq][row][k-in-quad]
    __shared__ float Bs[2][4][128][4];   // [buf][kq][col][k-in-quad]
    const unsigned asb = (unsigned)__cvta_generic_to_shared(&As[0][0][0][0]);
    const unsigned bsb = (unsigned)__cvta_generic_to_shared(&Bs[0][0][0][0]);

    int tid = threadIdx.x;
    int tx = tid & 31, ty = tid >> 5;
    int row0 = row_base + blockIdx.x * 128;

    // copy units: 1024 x 8B per tile per array; thread handles u and u+512
    int u0 = tid,        h0 = u0 & 1, m0 = (u0 >> 1) & 127, kq0 = u0 >> 8;
    int u1 = tid + 512,  h1 = u1 & 1, m1 = (u1 >> 1) & 127, kq1 = u1 >> 8;
    unsigned offA0 = (unsigned)(kq0 * 2048 + m0 * 16 + h0 * 8);
    unsigned offA1 = (unsigned)(kq1 * 2048 + m1 * 16 + h1 * 8);
    const float* zs0 = z + (row0 + m0) * DD + kq0 * 4 + h0 * 2;
    const float* zs1 = z + (row0 + m1) * DD + kq1 * 4 + h1 * 2;
    const float* cs0 = cb + m0 * DD + kq0 * 4 + h0 * 2;   // + col0*DD + dk later
    const float* cs1 = cb + m1 * DD + kq1 * 4 + h1 * 2;

    unsigned raoff = (unsigned)(ty * 4 * 16);      // rows ty*4.. (strip 0)
    unsigned rboff = (unsigned)(tx * 16);

    float bv[8], sv[8]; int bi[8];
    #pragma unroll
    for (int i = 0; i < 8; i++) { bv[i] = -3.4e38f; sv[i] = -3.4e38f; bi[i] = 0; }

    for (int chunk = 0; chunk < 4; chunk++) {
        int col0 = chunk * 128;
        const float* cc0 = cs0 + col0 * DD;
        const float* cc1 = cs1 + col0 * DD;

        unsigned long long acc2[8][4];
        #pragma unroll
        for (int i = 0; i < 8; i++)
            #pragma unroll
            for (int j = 0; j < 4; j++) acc2[i][j] = 0ull;

        __syncthreads();                 // prior buffer reads finished
        // preload tile 0 into buf 0
        cp8(asb + offA0, zs0); cp8(asb + offA1, zs1);
        cp8(bsb + offA0, cc0); cp8(bsb + offA1, cc1);
        cp_commit();

        int p = 0;
        for (int t = 0; t < 16; t++) {
            cp_wait0();
            __syncthreads();             // buf p fully resident for all threads
            if (t < 15) {
                int dk = (t + 1) * 16;
                unsigned qb = (unsigned)((p ^ 1) * 8192);
                cp8(asb + qb + offA0, zs0 + dk); cp8(asb + qb + offA1, zs1 + dk);
                cp8(bsb + qb + offA0, cc0 + dk); cp8(bsb + qb + offA1, cc1 + dk);
                cp_commit();
            }
            unsigned ab = asb + (unsigned)(p * 8192);
            unsigned bb = bsb + (unsigned)(p * 8192);
            #pragma unroll
            for (int kq = 0; kq < 4; kq++) {
                unsigned long long rb0[4], rb1[4];
                #pragma unroll
                for (int j = 0; j < 4; j++)
                    lds_v2u64(rb0[j], rb1[j], bb + kq * 2048 + rboff + j * 512);
                #pragma unroll
                for (int i = 0; i < 8; i++) {
                    unsigned roff = raoff + ((i < 4) ? (unsigned)(i * 16)
                                                     : (unsigned)(1024 + (i - 4) * 16));
                    unsigned long long ra0, ra1;
                    lds_v2u64(ra0, ra1, ab + kq * 2048 + roff);
                    #pragma unroll
                    for (int j = 0; j < 4; j++) {
                        ffma2(acc2[i][j], ra0, rb0[j]);
                        ffma2(acc2[i][j], ra1, rb1[j]);
                    }
                }
            }
            p ^= 1;
        }

        // epilogue: fold chunk scores into per-row top-2
        #pragma unroll
        for (int j = 0; j < 4; j++) {
            int c = col0 + tx + 32 * j;
            float hn = g_halfnorm[c];
            #pragma unroll
            for (int i = 0; i < 8; i++) {
                float2 pr = unpack2(acc2[i][j]);
                float s = (pr.x + pr.y) - hn;
                if (s > bv[i] || (s == bv[i] && c < bi[i])) { sv[i] = bv[i]; bv[i] = s; bi[i] = c; }
                else if (s > sv[i]) sv[i] = s;
            }
        }
    }

    // reduce (best, second) across the 32 lanes covering each row
    #pragma unroll
    for (int i = 0; i < 8; i++) {
        float v = bv[i], s2 = sv[i]; int idx = bi[i];
        #pragma unroll
        for (int off = 16; off > 0; off >>= 1) {
            float v2  = __shfl_xor_sync(0xffffffffu, v, off);
            float s22 = __shfl_xor_sync(0xffffffffu, s2, off);
            int   i2  = __shfl_xor_sync(0xffffffffu, idx, off);
            if (v2 > v || (v2 == v && i2 < idx)) { s2 = fmaxf(v, s22); v = v2; idx = i2; }
            else { s2 = fmaxf(s2, v2); }
        }
        if (tx == 0) {
            int lr = (i < 4) ? (ty * 4 + i) : (64 + ty * 4 + i - 4);
            int r = row0 + lr;
            g_enc[r] = idx;
            enc_f[r] = (float)idx;
            atomicAdd(&g_counts[idx], 1);
            if (v - s2 < 3e-4f) {            // near-tie: exact fp64 re-check
                int pfx = atomicAdd(&g_fixn, 1);
                if (pfx < 8192) g_fixrows[pfx] = r;
            }
        }
    }
}

// -------- exact fp64 re-argmax (dot form) for near-tie rows --------
__global__ void fixup_kernel(const float* __restrict__ z, const float* __restrict__ cb,
                             float* __restrict__ enc_f) {
    __shared__ double sval[256];
    __shared__ int    sidx[256];
    __shared__ float  zsh[DD];
    int nfix = min(g_fixn, 8192);
    int t = threadIdx.x;
    for (int e = blockIdx.x; e < nfix; e += gridDim.x) {
        int row = g_fixrows[e];
        zsh[t] = z[row * DD + t];
        __syncthreads();
        double bestv = -1e300; int besti = 0;
        #pragma unroll
        for (int kb = 0; kb < 2; kb++) {
            int k = t + kb * 256;
            const float* cr = cb + k * DD;
            double a0 = 0.0, a1 = 0.0, a2 = 0.0, a3 = 0.0;
            #pragma unroll 4
            for (int dd = 0; dd < DD; dd += 4) {
                a0 += (double)zsh[dd]     * (double)cr[dd];
                a1 += (double)zsh[dd + 1] * (double)cr[dd + 1];
                a2 += (double)zsh[dd + 2] * (double)cr[dd + 2];
                a3 += (double)zsh[dd + 3] * (double)cr[dd + 3];
            }
            double s = ((a0 + a1) + (a2 + a3)) - g_hnd[k];
            if (s > bestv || (s == bestv && k < besti)) { bestv = s; besti = k; }
        }
        sval[t] = bestv; sidx[t] = besti;
        __syncthreads();
        for (int off = 128; off > 0; off >>= 1) {
            if (t < off) {
                if (sval[t + off] > sval[t] ||
                    (sval[t + off] == sval[t] && sidx[t + off] < sidx[t])) {
                    sval[t] = sval[t + off]; sidx[t] = sidx[t + off];
                }
            }
            __syncthreads();
        }
        if (t == 0) {
            int old = g_enc[row];
            if (sidx[0] != old) {
                atomicSub(&g_counts[old], 1);
                atomicAdd(&g_counts[sidx[0]], 1);
                g_enc[row] = sidx[0];
                enc_f[row] = (float)sidx[0];
            }
        }
        __syncthreads();
    }
}

// -------- exclusive scan over 512 bins --------
__global__ void prefix_kernel() {
    __shared__ int a[KK];
    int t = threadIdx.x;
    int c = g_counts[t];
    a[t] = c;
    __syncthreads();
    for (int off = 1; off < KK; off <<= 1) {
        int v = (t >= off) ? a[t - off] : 0;
        __syncthreads();
        a[t] += v;
        __syncthreads();
    }
    int ex = a[t] - c;
    g_offsets[t] = ex;
    g_cursor[t] = ex;
}

// -------- scatter rows into per-code buckets --------
__global__ void scatter_kernel() {
    int stride = gridDim.x * blockDim.x;
    for (int i = blockIdx.x * blockDim.x + threadIdx.x; i < NR; i += stride) {
        int k = g_enc[i];
        int pos = atomicAdd(&g_cursor[k], 1);
        g_rowlist[pos] = i;
    }
}

// -------- per-code EMA: balanced partial sums (NSEG segments per code) --------
__global__ void update_partial_kernel(const float* __restrict__ z) {
    int k = blockIdx.x / NSEG, s = blockIdx.x % NSEG, t = threadIdx.x;
    int base = g_offsets[k];
    int cnt = g_counts[k];
    int lo = base + (int)((long long)cnt * s / NSEG);
    int hi = base + (int)((long long)cnt * (s + 1) / NSEG);
    float acc = 0.f;
    int i = lo;
    for (; i + 4 <= hi; i += 4) {
        int r0 = g_rowlist[i],     r1 = g_rowlist[i + 1];
        int r2 = g_rowlist[i + 2], r3 = g_rowlist[i + 3];
        float v0 = z[r0 * DD + t], v1 = z[r1 * DD + t];
        float v2 = z[r2 * DD + t], v3 = z[r3 * DD + t];
        acc += v0; acc += v1; acc += v2; acc += v3;
    }
    for (; i < hi; i++) acc += z[g_rowlist[i] * DD + t];
    g_epart[blockIdx.x * DD + t] = acc;
}

// -------- combine partials (fixed order), write e_new / cb_new / n_new --------
__global__ void update_reduce_kernel(const float* __restrict__ n_i,
                                     const float* __restrict__ e_i,
                                     float* __restrict__ out_e, float* __restrict__ out_cb,
                                     float* __restrict__ out_n) {
    int k = blockIdx.x, t = threadIdx.x;
    const float* pp = g_epart + (k * NSEG) * DD + t;
    float acc = 0.f;
    #pragma unroll
    for (int i = 0; i < NSEG; i += 4) {
        float s01 = pp[i * DD] + pp[(i + 1) * DD];
        float s23 = pp[(i + 2) * DD] + pp[(i + 3) * DD];
        acc += s01 + s23;
    }
    const float C1 = (float)(1.0 - 0.99);                   // 1 - DECAY
    const float NS = (float)(32.0 / (32.0 + 512.0 * 1e-5)); // b / (b + K*EPS)
    float nnew = (0.99f * n_i[k] + C1 * (float)g_counts[k] + 1e-5f) * NS;
    float enew = 0.99f * e_i[k * DD + t] + C1 * acc;
    out_e[k * DD + t]  = enew;
    out_cb[k * DD + t] = enew / nnew;
    if (t == 0) out_n[k] = nnew;
}

// -------- gather codes, STE output, commitment-loss partials (linear z) -------
__global__ void gather_kernel(const float* __restrict__ z, const float* __restrict__ cb,
                              float* __restrict__ out_code) {
    float part = 0.f;
    int stride = gridDim.x * blockDim.x;
    for (int idx = blockIdx.x * blockDim.x + threadIdx.x; idx < NV4; idx += stride) {
        float4 zv = ((const float4*)z)[idx];
        int row = idx >> 6;            // 64 float4 per row
        int d = (idx & 63) << 2;
        int k = g_enc[row];
        float4 cv = *(const float4*)(cb + k * DD + d);
        float4 o;
        o.x = zv.x + (cv.x - zv.x);
        o.y = zv.y + (cv.y - zv.y);
        o.z = zv.z + (cv.z - zv.z);
        o.w = zv.w + (cv.w - zv.w);
        ((float4*)out_code)[idx] = o;
        float dx = zv.x - cv.x, dy = zv.y - cv.y;
        float dz = zv.z - cv.z, dw = zv.w - cv.w;
        part += dx * dx + dy * dy + dz * dz + dw * dw;
    }
    #pragma unroll
    for (int o = 16; o > 0; o >>= 1) part += __shfl_xor_sync(0xffffffffu, part, o);
    __shared__ float sm[8];
    if ((threadIdx.x & 31) == 0) sm[threadIdx.x >> 5] = part;
    __syncthreads();
    if (threadIdx.x == 0) {
        float tot = 0.f;
        #pragma unroll
        for (int i = 0; i < 8; i++) tot += sm[i];
        g_losspart[blockIdx.x] = (double)tot;
    }
}

__global__ void finalize_kernel(float* __restrict__ out_loss) {
    __shared__ double sm[256];
    double s = 0.0;
    for (int i = threadIdx.x; i < 8192; i += 256) s += g_losspart[i];
    sm[threadIdx.x] = s;
    __syncthreads();
    for (int off = 128; off > 0; off >>= 1) {
        if (threadIdx.x < off) sm[threadIdx.x] += sm[threadIdx.x + off];
        __syncthreads();
    }
    if (threadIdx.x == 0) out_loss[0] = 0.25f * (float)(sm[0] / 33554432.0);
}

extern "C" void kernel_launch(void* const* d_in, const int* in_sizes, int n_in,
                              void* d_out, int out_size) {
    const float* z   = (const float*)d_in[0];
    const float* cb  = (const float*)d_in[1];
    const float* n_i = (const float*)d_in[2];
    const float* e_i = (const float*)d_in[3];
    float* out = (float*)d_out;

    halfnorm_kernel<<<KK, 256>>>(cb);                          // #1
    pad_kernel<<<1, 32>>>();                                   // #2
    argmin_kernel<<<512, 512>>>(z, cb, out + OFF_ENC, 0);      // #3  <- ncu
    argmin_kernel<<<512, 512>>>(z, cb, out + OFF_ENC, 65536);  // #4  <- ncu
    fixup_kernel<<<128, 256>>>(z, cb, out + OFF_ENC);          // #5
    prefix_kernel<<<1, KK>>>();                                // #6
    scatter_kernel<<<128, 256>>>();                            // #7
    update_partial_kernel<<<KK * NSEG, 256>>>(z);              // #8
    update_reduce_kernel<<<KK, 256>>>(n_i, e_i, out + OFF_E, out + OFF_CB, out + OFF_N);
    gather_kernel<<<8192, 256>>>(z, cb, out);
    finalize_kernel<<<1, 256>>>(out + OFF_LOSS);
}

// round 7
// speedup vs baseline: 3.8105x; 3.8105x over previous
#include <cuda_runtime.h>

// Problem constants (fixed shapes per reference):
//   z: [32,256,64,64] f32 -> flat [131072, 256]
//   codebook: [512, 256], n_i: [512], e_i: [512,256]
#define NR 131072
#define DD 256
#define KK 512
#define NV4 (NR * DD / 4)   // 8388608 float4 elements of z

// Output layout (concatenated reference tuple, all float32):
//   code_ste [33554432], loss [1], encoding [131072],
//   codebook_new [131072], n_new [512], e_new [131072]
#define OFF_LOSS 33554432
#define OFF_ENC  33554433
#define OFF_CB   33685505
#define OFF_N    33816577
#define OFF_E    33817089

#define NSEG 8    // segments per code for balanced EMA partial pass
#define PITCH 132 // smem row pitch: 16B-aligned rows, de-conflicted stores

// -------- device scratch (no allocations allowed) --------
static __device__ int    g_enc[NR];
static __device__ int    g_rowlist[NR];
static __device__ int    g_counts[KK];
static __device__ int    g_offsets[KK];
static __device__ int    g_cursor[KK];
static __device__ float  g_halfnorm[KK];
static __device__ double g_hnd[KK];
static __device__ int    g_fixn;
static __device__ int    g_fixrows[8192];
static __device__ float  g_epart[KK * NSEG * DD];
static __device__ double g_losspart[8192];

// -------- packed f32x2 helpers --------
__device__ __forceinline__ unsigned long long pack2_dup(float x) {
    unsigned long long r;
    asm("mov.b64 %0, {%1, %1};" : "=l"(r) : "f"(x));
    return r;
}
__device__ __forceinline__ void ffma2(unsigned long long& d, unsigned long long a,
                                      unsigned long long b) {
    asm("fma.rn.f32x2 %0, %1, %2, %0;" : "+l"(d) : "l"(a), "l"(b));
}
__device__ __forceinline__ float2 unpack2(unsigned long long v) {
    float2 p;
    asm("mov.b64 {%0, %1}, %2;" : "=f"(p.x), "=f"(p.y) : "l"(v));
    return p;
}

// -------- halfnorm + per-replay state init --------
__global__ void halfnorm_kernel(const float* __restrict__ cb) {
    int k = blockIdx.x;
    float v = cb[k * DD + threadIdx.x];
    double s = (double)v * (double)v;
    #pragma unroll
    for (int o = 16; o > 0; o >>= 1) s += __shfl_xor_sync(0xffffffffu, s, o);
    __shared__ double sm[8];
    if ((threadIdx.x & 31) == 0) sm[threadIdx.x >> 5] = s;
    __syncthreads();
    if (threadIdx.x == 0) {
        double tot = 0.0;
        #pragma unroll
        for (int i = 0; i < 8; i++) tot += sm[i];
        g_hnd[k] = 0.5 * tot;
        g_halfnorm[k] = (float)(0.5 * tot);
        g_counts[k] = 0;                    // per-replay zero (graph replays!)
        if (k == 0) g_fixn = 0;
    }
}

// -------- pad: places argmin at launches #3 and #4 (capture is one of them) ---
__global__ void pad_kernel() {}

// -------- fused GEMM + top-2 argmax (MEASURED-FAST R3 version) --------
// argmin dist == argmax (x.c - 0.5||c||^2). Block: 128 rows x all 512 codes
// (4 chunks of 128). 256 threads (16x16); per-thread tile: rows {ty*4+0..3,
// 64+ty*4+0..3} x cols {tx*4+0..3, 64+tx*4+0..3}. BK=16, double-buffered SMEM,
// register-staged global prefetch. FFMA2 inner product (2 cols per op).
__global__ __launch_bounds__(256, 1) void argmin_kernel(
        const float* __restrict__ z, const float* __restrict__ cb,
        float* __restrict__ enc_f, int row_base) {
    __shared__ float As[2][16][PITCH];
    __shared__ float Bs[2][16][PITCH];
    int tid = threadIdx.x;
    int tx = tid & 15, ty = tid >> 4;
    int tx4 = tx * 4, ty4 = ty * 4;
    int row0 = row_base + blockIdx.x * 128;

    // global load indices: f = tid + l*256 -> m = f>>2 (row/col), kq = f&3
    int m0 = tid >> 2, kq0 = tid & 3;
    int m1 = (tid + 256) >> 2, kq1 = kq0;

    float bv[8], sv[8]; int bi[8];
    #pragma unroll
    for (int i = 0; i < 8; i++) { bv[i] = -3.4e38f; sv[i] = -3.4e38f; bi[i] = 0; }

    for (int chunk = 0; chunk < 4; chunk++) {
        int col0 = chunk * 128;
        unsigned long long acc2[8][4];
        #pragma unroll
        for (int i = 0; i < 8; i++)
            #pragma unroll
            for (int j = 0; j < 4; j++) acc2[i][j] = 0ull;

        // preload dk=0 tile
        {
            float4 a0 = *(const float4*)(z  + (row0 + m0) * DD + kq0 * 4);
            float4 b0 = *(const float4*)(cb + (col0 + m0) * DD + kq0 * 4);
            float4 a1 = *(const float4*)(z  + (row0 + m1) * DD + kq1 * 4);
            float4 b1 = *(const float4*)(cb + (col0 + m1) * DD + kq1 * 4);
            As[0][kq0*4+0][m0] = a0.x; As[0][kq0*4+1][m0] = a0.y;
            As[0][kq0*4+2][m0] = a0.z; As[0][kq0*4+3][m0] = a0.w;
            Bs[0][kq0*4+0][m0] = b0.x; Bs[0][kq0*4+1][m0] = b0.y;
            Bs[0][kq0*4+2][m0] = b0.z; Bs[0][kq0*4+3][m0] = b0.w;
            As[0][kq1*4+0][m1] = a1.x; As[0][kq1*4+1][m1] = a1.y;
            As[0][kq1*4+2][m1] = a1.z; As[0][kq1*4+3][m1] = a1.w;
            Bs[0][kq1*4+0][m1] = b1.x; Bs[0][kq1*4+1][m1] = b1.y;
            Bs[0][kq1*4+2][m1] = b1.z; Bs[0][kq1*4+3][m1] = b1.w;
        }
        __syncthreads();

        int p = 0;
        for (int dkb = 0; dkb < 16; dkb++) {
            // prefetch next dk tile into registers (no smem touch yet)
            float4 a0, b0, a1, b1;
            bool has = (dkb < 15);
            if (has) {
                int dk = (dkb + 1) * 16;
                a0 = *(const float4*)(z  + (row0 + m0) * DD + dk + kq0 * 4);
                b0 = *(const float4*)(cb + (col0 + m0) * DD + dk + kq0 * 4);
                a1 = *(const float4*)(z  + (row0 + m1) * DD + dk + kq1 * 4);
                b1 = *(const float4*)(cb + (col0 + m1) * DD + dk + kq1 * 4);
            }
            // compute on buffer p
            #pragma unroll
            for (int kk = 0; kk < 16; kk++) {
                float4 ral = *(const float4*)&As[p][kk][ty4];
                float4 rah = *(const float4*)&As[p][kk][64 + ty4];
                ulonglong2 rbl = *(const ulonglong2*)&Bs[p][kk][tx4];
                ulonglong2 rbh = *(const ulonglong2*)&Bs[p][kk][64 + tx4];
                float ra[8] = {ral.x, ral.y, ral.z, ral.w, rah.x, rah.y, rah.z, rah.w};
                #pragma unroll
                for (int i = 0; i < 8; i++) {
                    unsigned long long d = pack2_dup(ra[i]);
                    ffma2(acc2[i][0], d, rbl.x);
                    ffma2(acc2[i][1], d, rbl.y);
                    ffma2(acc2[i][2], d, rbh.x);
                    ffma2(acc2[i][3], d, rbh.y);
                }
            }
            if (has) {
                int q = p ^ 1;
                As[q][kq0*4+0][m0] = a0.x; As[q][kq0*4+1][m0] = a0.y;
                As[q][kq0*4+2][m0] = a0.z; As[q][kq0*4+3][m0] = a0.w;
                Bs[q][kq0*4+0][m0] = b0.x; Bs[q][kq0*4+1][m0] = b0.y;
                Bs[q][kq0*4+2][m0] = b0.z; Bs[q][kq0*4+3][m0] = b0.w;
                As[q][kq1*4+0][m1] = a1.x; As[q][kq1*4+1][m1] = a1.y;
                As[q][kq1*4+2][m1] = a1.z; As[q][kq1*4+3][m1] = a1.w;
                Bs[q][kq1*4+0][m1] = b1.x; Bs[q][kq1*4+1][m1] = b1.y;
                Bs[q][kq1*4+2][m1] = b1.z; Bs[q][kq1*4+3][m1] = b1.w;
            }
            __syncthreads();
            p ^= 1;
        }

        // epilogue: fold this chunk's 16 score-columns into per-row top-2
        float4 hnl = *(const float4*)&g_halfnorm[col0 + tx4];
        float4 hnh = *(const float4*)&g_halfnorm[col0 + 64 + tx4];
        float hn[8] = {hnl.x, hnl.y, hnl.z, hnl.w, hnh.x, hnh.y, hnh.z, hnh.w};
        #pragma unroll
        for (int i = 0; i < 8; i++) {
            #pragma unroll
            for (int j = 0; j < 4; j++) {
                float2 pr = unpack2(acc2[i][j]);
                int g = j >> 1;                       // 0: low strip, 1: high strip
                int cbase = col0 + g * 64 + tx4 + (j & 1) * 2;
                float s0 = pr.x - hn[g * 4 + (j & 1) * 2];
                float s1 = pr.y - hn[g * 4 + (j & 1) * 2 + 1];
                if (s0 > bv[i] || (s0 == bv[i] && cbase < bi[i])) { sv[i] = bv[i]; bv[i] = s0; bi[i] = cbase; }
                else if (s0 > sv[i]) sv[i] = s0;
                int c1 = cbase + 1;
                if (s1 > bv[i] || (s1 == bv[i] && c1 < bi[i])) { sv[i] = bv[i]; bv[i] = s1; bi[i] = c1; }
                else if (s1 > sv[i]) sv[i] = s1;
            }
        }
    }
    // reduce (best, second) across the 16 tx-lanes covering each row
    #pragma unroll
    for (int i = 0; i < 8; i++) {
        float v = bv[i], s2 = sv[i]; int idx = bi[i];
        #pragma unroll
        for (int off = 8; off > 0; off >>= 1) {
            float v2  = __shfl_xor_sync(0xffffffffu, v, off);
            float s22 = __shfl_xor_sync(0xffffffffu, s2, off);
            int   i2  = __shfl_xor_sync(0xffffffffu, idx, off);
            if (v2 > v || (v2 == v && i2 < idx)) { s2 = fmaxf(v, s22); v = v2; idx = i2; }
            else { s2 = fmaxf(s2, v2); }
        }
        if (tx == 0) {
            int lr = (i < 4) ? (ty4 + i) : (64 + ty4 + i - 4);
            int r = row0 + lr;
            g_enc[r] = idx;
            enc_f[r] = (float)idx;
            atomicAdd(&g_counts[idx], 1);
            if (v - s2 < 3e-4f) {            // near-tie: exact fp64 re-check
                int pfx = atomicAdd(&g_fixn, 1);
                if (pfx < 8192) g_fixrows[pfx] = r;
            }
        }
    }
}

// -------- exact fp64 re-argmax (dot form) for near-tie rows --------
__global__ void fixup_kernel(const float* __restrict__ z, const float* __restrict__ cb,
                             float* __restrict__ enc_f) {
    __shared__ double sval[256];
    __shared__ int    sidx[256];
    __shared__ float  zsh[DD];
    int nfix = min(g_fixn, 8192);
    int t = threadIdx.x;
    for (int e = blockIdx.x; e < nfix; e += gridDim.x) {
        int row = g_fixrows[e];
        zsh[t] = z[row * DD + t];
        __syncthreads();
        double bestv = -1e300; int besti = 0;
        #pragma unroll
        for (int kb = 0; kb < 2; kb++) {
            int k = t + kb * 256;
            const float* cr = cb + k * DD;
            double a0 = 0.0, a1 = 0.0, a2 = 0.0, a3 = 0.0;
            #pragma unroll 4
            for (int dd = 0; dd < DD; dd += 4) {
                a0 += (double)zsh[dd]     * (double)cr[dd];
                a1 += (double)zsh[dd + 1] * (double)cr[dd + 1];
                a2 += (double)zsh[dd + 2] * (double)cr[dd + 2];
                a3 += (double)zsh[dd + 3] * (double)cr[dd + 3];
            }
            double s = ((a0 + a1) + (a2 + a3)) - g_hnd[k];
            if (s > bestv || (s == bestv && k < besti)) { bestv = s; besti = k; }
        }
        sval[t] = bestv; sidx[t] = besti;
        __syncthreads();
        for (int off = 128; off > 0; off >>= 1) {
            if (t < off) {
                if (sval[t + off] > sval[t] ||
                    (sval[t + off] == sval[t] && sidx[t + off] < sidx[t])) {
                    sval[t] = sval[t + off]; sidx[t] = sidx[t + off];
                }
            }
            __syncthreads();
        }
        if (t == 0) {
            int old = g_enc[row];
            if (sidx[0] != old) {
                atomicSub(&g_counts[old], 1);
                atomicAdd(&g_counts[sidx[0]], 1);
                g_enc[row] = sidx[0];
                enc_f[row] = (float)sidx[0];
            }
        }
        __syncthreads();
    }
}

// -------- exclusive scan over 512 bins --------
__global__ void prefix_kernel() {
    __shared__ int a[KK];
    int t = threadIdx.x;
    int c = g_counts[t];
    a[t] = c;
    __syncthreads();
    for (int off = 1; off < KK; off <<= 1) {
        int v = (t >= off) ? a[t - off] : 0;
        __syncthreads();
        a[t] += v;
        __syncthreads();
    }
    int ex = a[t] - c;
    g_offsets[t] = ex;
    g_cursor[t] = ex;
}

// -------- scatter rows into per-code buckets --------
__global__ void scatter_kernel() {
    int stride = gridDim.x * blockDim.x;
    for (int i = blockIdx.x * blockDim.x + threadIdx.x; i < NR; i += stride) {
        int k = g_enc[i];
        int pos = atomicAdd(&g_cursor[k], 1);
        g_rowlist[pos] = i;
    }
}

// -------- per-code EMA: balanced partial sums (NSEG segments per code) --------
__global__ void update_partial_kernel(const float* __restrict__ z) {
    int k = blockIdx.x / NSEG, s = blockIdx.x % NSEG, t = threadIdx.x;
    int base = g_offsets[k];
    int cnt = g_counts[k];
    int lo = base + (int)((long long)cnt * s / NSEG);
    int hi = base + (int)((long long)cnt * (s + 1) / NSEG);
    float acc = 0.f;
    int i = lo;
    for (; i + 4 <= hi; i += 4) {
        int r0 = g_rowlist[i],     r1 = g_rowlist[i + 1];
        int r2 = g_rowlist[i + 2], r3 = g_rowlist[i + 3];
        float v0 = z[r0 * DD + t], v1 = z[r1 * DD + t];
        float v2 = z[r2 * DD + t], v3 = z[r3 * DD + t];
        acc += v0; acc += v1; acc += v2; acc += v3;
    }
    for (; i < hi; i++) acc += z[g_rowlist[i] * DD + t];
    g_epart[blockIdx.x * DD + t] = acc;
}

// -------- combine partials (fixed order), write e_new / cb_new / n_new --------
__global__ void update_reduce_kernel(const float* __restrict__ n_i,
                                     const float* __restrict__ e_i,
                                     float* __restrict__ out_e, float* __restrict__ out_cb,
                                     float* __restrict__ out_n) {
    int k = blockIdx.x, t = threadIdx.x;
    const float* pp = g_epart + (k * NSEG) * DD + t;
    float acc = 0.f;
    #pragma unroll
    for (int i = 0; i < NSEG; i += 4) {
        float s01 = pp[i * DD] + pp[(i + 1) * DD];
        float s23 = pp[(i + 2) * DD] + pp[(i + 3) * DD];
        acc += s01 + s23;
    }
    const float C1 = (float)(1.0 - 0.99);                   // 1 - DECAY
    const float NS = (float)(32.0 / (32.0 + 512.0 * 1e-5)); // b / (b + K*EPS)
    float nnew = (0.99f * n_i[k] + C1 * (float)g_counts[k] + 1e-5f) * NS;
    float enew = 0.99f * e_i[k * DD + t] + C1 * acc;
    out_e[k * DD + t]  = enew;
    out_cb[k * DD + t] = enew / nnew;
    if (t == 0) out_n[k] = nnew;
}

// -------- gather codes, STE output, commitment-loss partials (linear z) -------
__global__ void gather_kernel(const float* __restrict__ z, const float* __restrict__ cb,
                              float* __restrict__ out_code) {
    float part = 0.f;
    int stride = gridDim.x * blockDim.x;
    for (int idx = blockIdx.x * blockDim.x + threadIdx.x; idx < NV4; idx += stride) {
        float4 zv = ((const float4*)z)[idx];
        int row = idx >> 6;            // 64 float4 per row
        int d = (idx & 63) << 2;
        int k = g_enc[row];
        float4 cv = *(const float4*)(cb + k * DD + d);
        float4 o;
        o.x = zv.x + (cv.x - zv.x);
        o.y = zv.y + (cv.y - zv.y);
        o.z = zv.z + (cv.z - zv.z);
        o.w = zv.w + (cv.w - zv.w);
        ((float4*)out_code)[idx] = o;
        float dx = zv.x - cv.x, dy = zv.y - cv.y;
        float dz = zv.z - cv.z, dw = zv.w - cv.w;
        part += dx * dx + dy * dy + dz * dz + dw * dw;
    }
    #pragma unroll
    for (int o = 16; o > 0; o >>= 1) part += __shfl_xor_sync(0xffffffffu, part, o);
    __shared__ float sm[8];
    if ((threadIdx.x & 31) == 0) sm[threadIdx.x >> 5] = part;
    __syncthreads();
    if (threadIdx.x == 0) {
        float tot = 0.f;
        #pragma unroll
        for (int i = 0; i < 8; i++) tot += sm[i];
        g_losspart[blockIdx.x] = (double)tot;
    }
}

__global__ void finalize_kernel(float* __restrict__ out_loss) {
    __shared__ double sm[256];
    double s = 0.0;
    for (int i = threadIdx.x; i < 8192; i += 256) s += g_losspart[i];
    sm[threadIdx.x] = s;
    __syncthreads();
    for (int off = 128; off > 0; off >>= 1) {
        if (threadIdx.x < off) sm[threadIdx.x] += sm[threadIdx.x + off];
        __syncthreads();
    }
    if (threadIdx.x == 0) out_loss[0] = 0.25f * (float)(sm[0] / 33554432.0);
}

extern "C" void kernel_launch(void* const* d_in, const int* in_sizes, int n_in,
                              void* d_out, int out_size) {
    const float* z   = (const float*)d_in[0];
    const float* cb  = (const float*)d_in[1];
    const float* n_i = (const float*)d_in[2];
    const float* e_i = (const float*)d_in[3];
    float* out = (float*)d_out;

    halfnorm_kernel<<<KK, 256>>>(cb);                          // #1
    pad_kernel<<<1, 32>>>();                                   // #2
    argmin_kernel<<<512, 256>>>(z, cb, out + OFF_ENC, 0);      // #3  <- ncu
    argmin_kernel<<<512, 256>>>(z, cb, out + OFF_ENC, 65536);  // #4  <- ncu
    fixup_kernel<<<128, 256>>>(z, cb, out + OFF_ENC);          // #5
    prefix_kernel<<<1, KK>>>();                                // #6
    scatter_kernel<<<128, 256>>>();                            // #7
    update_partial_kernel<<<KK * NSEG, 256>>>(z);              // #8
    update_reduce_kernel<<<KK, 256>>>(n_i, e_i, out + OFF_E, out + OFF_CB, out + OFF_N);
    gather_kernel<<<8192, 256>>>(z, cb, out);
    finalize_kernel<<<1, 256>>>(out + OFF_LOSS);
}

// round 9
// speedup vs baseline: 5.8641x; 1.5389x over previous
#include <cuda_runtime.h>
#include <cuda_bf16.h>

// Problem constants (fixed shapes per reference):
//   z: [32,256,64,64] f32 -> flat [131072, 256]
//   codebook: [512, 256], n_i: [512], e_i: [512,256]
#define NR 131072
#define DD 256
#define KK 512
#define NV4 (NR * DD / 4)

// Output layout (concatenated reference tuple, all float32):
#define OFF_LOSS 33554432
#define OFF_ENC  33554433
#define OFF_CB   33685505
#define OFF_N    33816577
#define OFF_E    33817089

#define NSEG 8
#define PITCH_B 80   // bytes per 32-bf16 row (64B data + 16B pad): ldmatrix conflict-free

// -------- device scratch (no allocations allowed) --------
static __device__ int    g_enc[NR];
static __device__ int    g_rowlist[NR];
static __device__ int    g_counts[KK];
static __device__ int    g_offsets[KK];
static __device__ int    g_cursor[KK];
static __device__ float  g_halfnorm[KK];
static __device__ double g_hnd[KK];
static __device__ int    g_fixn;
static __device__ int    g_fixrows[8192];
static __device__ float  g_epart[KK * NSEG * DD];
static __device__ double g_losspart[8192];
static __device__ __nv_bfloat16 g_cbhi[KK * DD];
static __device__ __nv_bfloat16 g_cblo[KK * DD];

// -------- PTX helpers --------
__device__ __forceinline__ unsigned smem_u32(const void* p) {
    unsigned a;
    asm("{ .reg .u64 t; cvta.to.shared.u64 t, %1; cvt.u32.u64 %0, t; }"
        : "=r"(a) : "l"(p));
    return a;
}
__device__ __forceinline__ void cp16(unsigned dst, const void* src) {
    asm volatile("cp.async.cg.shared.global [%0], [%1], 16;"
                 :: "r"(dst), "l"(__cvta_generic_to_global(src)));
}
__device__ __forceinline__ void cp_commit() { asm volatile("cp.async.commit_group;"); }
__device__ __forceinline__ void cp_wait0()  { asm volatile("cp.async.wait_group 0;"); }

__device__ __forceinline__ void ldm_x4(unsigned* r, unsigned addr) {
    asm volatile("ldmatrix.sync.aligned.m8n8.x4.shared.b16 {%0,%1,%2,%3}, [%4];"
                 : "=r"(r[0]), "=r"(r[1]), "=r"(r[2]), "=r"(r[3]) : "r"(addr));
}
__device__ __forceinline__ void mma16816(float* c, const unsigned* a,
                                         unsigned b0, unsigned b1) {
    asm volatile(
        "mma.sync.aligned.m16n8k16.row.col.f32.bf16.bf16.f32 "
        "{%0,%1,%2,%3}, {%4,%5,%6,%7}, {%8,%9}, {%0,%1,%2,%3};"
        : "+f"(c[0]), "+f"(c[1]), "+f"(c[2]), "+f"(c[3])
        : "r"(a[0]), "r"(a[1]), "r"(a[2]), "r"(a[3]), "r"(b0), "r"(b1));
}
__device__ __forceinline__ uint2 bf16x4_hi(float4 v, uint2& lo) {
    __nv_bfloat16 hx = __float2bfloat16(v.x), hy = __float2bfloat16(v.y);
    __nv_bfloat16 hz = __float2bfloat16(v.z), hw = __float2bfloat16(v.w);
    __nv_bfloat16 lx = __float2bfloat16(v.x - __bfloat162float(hx));
    __nv_bfloat16 ly = __float2bfloat16(v.y - __bfloat162float(hy));
    __nv_bfloat16 lz = __float2bfloat16(v.z - __bfloat162float(hz));
    __nv_bfloat16 lw = __float2bfloat16(v.w - __bfloat162float(hw));
    uint2 hi;
    hi.x = ((unsigned)__bfloat16_as_ushort(hy) << 16) | __bfloat16_as_ushort(hx);
    hi.y = ((unsigned)__bfloat16_as_ushort(hw) << 16) | __bfloat16_as_ushort(hz);
    lo.x = ((unsigned)__bfloat16_as_ushort(ly) << 16) | __bfloat16_as_ushort(lx);
    lo.y = ((unsigned)__bfloat16_as_ushort(lw) << 16) | __bfloat16_as_ushort(lz);
    return hi;
}

// -------- halfnorm + per-replay state init --------
__global__ void halfnorm_kernel(const float* __restrict__ cb) {
    int k = blockIdx.x;
    float v = cb[k * DD + threadIdx.x];
    double s = (double)v * (double)v;
    #pragma unroll
    for (int o = 16; o > 0; o >>= 1) s += __shfl_xor_sync(0xffffffffu, s, o);
    __shared__ double sm[8];
    if ((threadIdx.x & 31) == 0) sm[threadIdx.x >> 5] = s;
    __syncthreads();
    if (threadIdx.x == 0) {
        double tot = 0.0;
        #pragma unroll
        for (int i = 0; i < 8; i++) tot += sm[i];
        g_hnd[k] = 0.5 * tot;
        g_halfnorm[k] = (float)(0.5 * tot);
        g_counts[k] = 0;
        if (k == 0) g_fixn = 0;
    }
}

// -------- codebook -> bf16 hi/lo splits (global, row-major) --------
__global__ void cbconvert_kernel(const float* __restrict__ cb) {
    int i = blockIdx.x * 256 + threadIdx.x;   // 512 blocks x 256 = 131072
    float v = cb[i];
    __nv_bfloat16 h = __float2bfloat16(v);
    g_cbhi[i] = h;
    g_cblo[i] = __float2bfloat16(v - __bfloat162float(h));
}

// -------- HMMA bf16-split scoring + per-row argmax(top-2) --------
// S = z_hi.c_hi + z_hi.c_lo + z_lo.c_hi (fp32 accum). score = S - 0.5||c||^2.
// CTA: 128 rows x 512 codes; 4 col-chunks of 128; K staged in tiles of 32.
// 8 warps; warp w owns rows [w*16, w*16+16). mma.m16n8k16 + ldmatrix.
__global__ __launch_bounds__(256) void argmin_tc_kernel(
        const float* __restrict__ z, float* __restrict__ enc_f, int row_base) {
    __shared__ __align__(16) unsigned char sAhi[128 * PITCH_B];
    __shared__ __align__(16) unsigned char sAlo[128 * PITCH_B];
    __shared__ __align__(16) unsigned char sBhi[128 * PITCH_B];
    __shared__ __align__(16) unsigned char sBlo[128 * PITCH_B];
    __shared__ float shn[KK];

    const unsigned ahi = smem_u32(sAhi), alo = smem_u32(sAlo);
    const unsigned bhi = smem_u32(sBhi), blo = smem_u32(sBlo);

    int tid = threadIdx.x, wid = tid >> 5, l = tid & 31;
    int row0 = row_base + blockIdx.x * 128;

    shn[tid] = g_halfnorm[tid];
    shn[tid + 256] = g_halfnorm[tid + 256];

    // per-lane ldmatrix base offsets
    unsigned aoff = (unsigned)(((wid << 4) + (l & 15)) * PITCH_B + ((l >> 4) << 4));
    unsigned boff = (unsigned)((((l & 7) + ((l >> 4) << 3)) * PITCH_B) + (((l >> 3) & 1) << 4));

    // A staging indices (4 float4 units): unit u -> row u>>3, quad u&7
    // B staging indices (4 cp16 units over both splits)
    float bv[2], sv[2]; int bi[2];
    bv[0] = bv[1] = -3.4e38f; sv[0] = sv[1] = -3.4e38f; bi[0] = bi[1] = 0;

    for (int chunk = 0; chunk < 4; chunk++) {
        int col0 = chunk * 128;
        float acc[16][4];
        #pragma unroll
        for (int n = 0; n < 16; n++)
            #pragma unroll
            for (int q = 0; q < 4; q++) acc[n][q] = 0.f;

        for (int kt = 0; kt < 8; kt++) {          // K tiles of 32
            __syncthreads();                      // readers done with smem
            // stage B via cp.async (both splits)
            #pragma unroll
            for (int i = 0; i < 4; i++) {
                int u = tid + i * 256;            // 0..1023
                int split = u >> 9, uu = u & 511;
                int code = uu >> 2, c = uu & 3;
                const __nv_bfloat16* src = (split ? g_cblo : g_cbhi)
                    + (col0 + code) * DD + kt * 32 + c * 8;
                cp16((split ? blo : bhi) + (unsigned)(code * PITCH_B + c * 16), src);
            }
            cp_commit();
            // stage A: LDG f32 -> bf16 hi/lo -> STS (pitch 80)
            #pragma unroll
            for (int i = 0; i < 4; i++) {
                int u = tid + i * 256;            // 0..1023
                int row = u >> 3, c = u & 7;      // 8 float4 per 32-k row
                float4 v = *(const float4*)(z + (long)(row0 + row) * DD + kt * 32 + c * 4);
                uint2 lo, hi = bf16x4_hi(v, lo);
                unsigned off = (unsigned)(row * PITCH_B + c * 8);
                *(uint2*)(sAhi + off) = hi;
                *(uint2*)(sAlo + off) = lo;
            }
            cp_wait0();
            __syncthreads();

            #pragma unroll
            for (int ks = 0; ks < 2; ks++) {      // two k16 steps per tile
                unsigned kb = (unsigned)(ks << 5);    // k0*2 bytes
                unsigned ah[4], al[4];
                ldm_x4(ah, ahi + aoff + kb);
                ldm_x4(al, alo + aoff + kb);
                #pragma unroll
                for (int p = 0; p < 8; p++) {
                    unsigned bh[4], bl[4];
                    unsigned bo = boff + (unsigned)(p * 16 * PITCH_B) + kb;
                    ldm_x4(bh, bhi + bo);
                    ldm_x4(bl, blo + bo);
                    mma16816(acc[2*p],   ah, bh[0], bh[1]);
                    mma16816(acc[2*p+1], ah, bh[2], bh[3]);
                    mma16816(acc[2*p],   ah, bl[0], bl[1]);
                    mma16816(acc[2*p+1], ah, bl[2], bl[3]);
                    mma16816(acc[2*p],   al, bh[0], bh[1]);
                    mma16816(acc[2*p+1], al, bh[2], bh[3]);
                }
            }
        }

        // epilogue: fold chunk scores into per-row top-2
        #pragma unroll
        for (int nt = 0; nt < 16; nt++) {
            int c0 = col0 + nt * 8 + ((l & 3) << 1);
            float2 hn2 = *(const float2*)&shn[c0];
            float s00 = acc[nt][0] - hn2.x, s01 = acc[nt][1] - hn2.y;
            float s10 = acc[nt][2] - hn2.x, s11 = acc[nt][3] - hn2.y;
            if (s00 > bv[0]) { sv[0] = bv[0]; bv[0] = s00; bi[0] = c0; }
            else if (s00 > sv[0]) sv[0] = s00;
            if (s01 > bv[0]) { sv[0] = bv[0]; bv[0] = s01; bi[0] = c0 + 1; }
            else if (s01 > sv[0]) sv[0] = s01;
            if (s10 > bv[1]) { sv[1] = bv[1]; bv[1] = s10; bi[1] = c0; }
            else if (s10 > sv[1]) sv[1] = s10;
            if (s11 > bv[1]) { sv[1] = bv[1]; bv[1] = s11; bi[1] = c0 + 1; }
            else if (s11 > sv[1]) sv[1] = s11;
        }
    }

    // reduce across the 4 lanes (l^1, l^2) sharing each row
    #pragma unroll
    for (int r = 0; r < 2; r++) {
        float v = bv[r], s2 = sv[r]; int idx = bi[r];
        #pragma unroll
        for (int off = 1; off <= 2; off <<= 1) {
            float v2  = __shfl_xor_sync(0xffffffffu, v, off);
            float s22 = __shfl_xor_sync(0xffffffffu, s2, off);
            int   i2  = __shfl_xor_sync(0xffffffffu, idx, off);
            if (v2 > v || (v2 == v && i2 < idx)) { s2 = fmaxf(v, s22); v = v2; idx = i2; }
            else { s2 = fmaxf(s2, v2); }
        }
        if ((l & 3) == 0) {
            int row = row0 + (wid << 4) + (l >> 2) + r * 8;
            g_enc[row] = idx;
            enc_f[row] = (float)idx;
            atomicAdd(&g_counts[idx], 1);
            if (v - s2 < 5e-4f) {                // near-tie: exact fp64 re-check
                int p = atomicAdd(&g_fixn, 1);
                if (p < 8192) g_fixrows[p] = row;
            }
        }
    }
}

// -------- exact fp64 re-argmax (dot form) for near-tie rows --------
__global__ void fixup_kernel(const float* __restrict__ z, const float* __restrict__ cb,
                             float* __restrict__ enc_f) {
    __shared__ double sval[256];
    __shared__ int    sidx[256];
    __shared__ float  zsh[DD];
    int nfix = min(g_fixn, 8192);
    int t = threadIdx.x;
    for (int e = blockIdx.x; e < nfix; e += gridDim.x) {
        int row = g_fixrows[e];
        zsh[t] = z[row * DD + t];
        __syncthreads();
        double bestv = -1e300; int besti = 0;
        #pragma unroll
        for (int kb = 0; kb < 2; kb++) {
            int k = t + kb * 256;
            const float* cr = cb + k * DD;
            double a0 = 0.0, a1 = 0.0, a2 = 0.0, a3 = 0.0;
            #pragma unroll 4
            for (int dd = 0; dd < DD; dd += 4) {
                a0 += (double)zsh[dd]     * (double)cr[dd];
                a1 += (double)zsh[dd + 1] * (double)cr[dd + 1];
                a2 += (double)zsh[dd + 2] * (double)cr[dd + 2];
                a3 += (double)zsh[dd + 3] * (double)cr[dd + 3];
            }
            double s = ((a0 + a1) + (a2 + a3)) - g_hnd[k];
            if (s > bestv || (s == bestv && k < besti)) { bestv = s; besti = k; }
        }
        sval[t] = bestv; sidx[t] = besti;
        __syncthreads();
        for (int off = 128; off > 0; off >>= 1) {
            if (t < off) {
                if (sval[t + off] > sval[t] ||
                    (sval[t + off] == sval[t] && sidx[t + off] < sidx[t])) {
                    sval[t] = sval[t + off]; sidx[t] = sidx[t + off];
                }
            }
            __syncthreads();
        }
        if (t == 0) {
            int old = g_enc[row];
            if (sidx[0] != old) {
                atomicSub(&g_counts[old], 1);
                atomicAdd(&g_counts[sidx[0]], 1);
                g_enc[row] = sidx[0];
                enc_f[row] = (float)sidx[0];
            }
        }
        __syncthreads();
    }
}

// -------- exclusive scan over 512 bins --------
__global__ void prefix_kernel() {
    __shared__ int a[KK];
    int t = threadIdx.x;
    int c = g_counts[t];
    a[t] = c;
    __syncthreads();
    for (int off = 1; off < KK; off <<= 1) {
        int v = (t >= off) ? a[t - off] : 0;
        __syncthreads();
        a[t] += v;
        __syncthreads();
    }
    int ex = a[t] - c;
    g_offsets[t] = ex;
    g_cursor[t] = ex;
}

// -------- scatter rows into per-code buckets --------
__global__ void scatter_kernel() {
    int stride = gridDim.x * blockDim.x;
    for (int i = blockIdx.x * blockDim.x + threadIdx.x; i < NR; i += stride) {
        int k = g_enc[i];
        int pos = atomicAdd(&g_cursor[k], 1);
        g_rowlist[pos] = i;
    }
}

// -------- per-code EMA: balanced partial sums --------
__global__ void update_partial_kernel(const float* __restrict__ z) {
    int k = blockIdx.x / NSEG, s = blockIdx.x % NSEG, t = threadIdx.x;
    int base = g_offsets[k];
    int cnt = g_counts[k];
    int lo = base + (int)((long long)cnt * s / NSEG);
    int hi = base + (int)((long long)cnt * (s + 1) / NSEG);
    float acc = 0.f;
    int i = lo;
    for (; i + 4 <= hi; i += 4) {
        int r0 = g_rowlist[i],     r1 = g_rowlist[i + 1];
        int r2 = g_rowlist[i + 2], r3 = g_rowlist[i + 3];
        float v0 = z[r0 * DD + t], v1 = z[r1 * DD + t];
        float v2 = z[r2 * DD + t], v3 = z[r3 * DD + t];
        acc += v0; acc += v1; acc += v2; acc += v3;
    }
    for (; i < hi; i++) acc += z[g_rowlist[i] * DD + t];
    g_epart[blockIdx.x * DD + t] = acc;
}

// -------- combine partials, write e_new / cb_new / n_new --------
__global__ void update_reduce_kernel(const float* __restrict__ n_i,
                                     const float* __restrict__ e_i,
                                     float* __restrict__ out_e, float* __restrict__ out_cb,
                                     float* __restrict__ out_n) {
    int k = blockIdx.x, t = threadIdx.x;
    const float* pp = g_epart + (k * NSEG) * DD + t;
    float acc = 0.f;
    #pragma unroll
    for (int i = 0; i < NSEG; i += 4) {
        float s01 = pp[i * DD] + pp[(i + 1) * DD];
        float s23 = pp[(i + 2) * DD] + pp[(i + 3) * DD];
        acc += s01 + s23;
    }
    const float C1 = (float)(1.0 - 0.99);
    const float NS = (float)(32.0 / (32.0 + 512.0 * 1e-5));
    float nnew = (0.99f * n_i[k] + C1 * (float)g_counts[k] + 1e-5f) * NS;
    float enew = 0.99f * e_i[k * DD + t] + C1 * acc;
    out_e[k * DD + t]  = enew;
    out_cb[k * DD + t] = enew / nnew;
    if (t == 0) out_n[k] = nnew;
}

// -------- gather codes, STE output, commitment-loss partials (linear z) -------
__global__ void gather_kernel(const float* __restrict__ z, const float* __restrict__ cb,
                              float* __restrict__ out_code) {
    float part = 0.f;
    int stride = gridDim.x * blockDim.x;
    for (int idx = blockIdx.x * blockDim.x + threadIdx.x; idx < NV4; idx += stride) {
        float4 zv = ((const float4*)z)[idx];
        int row = idx >> 6;
        int d = (idx & 63) << 2;
        int k = g_enc[row];
        float4 cv = *(const float4*)(cb + k * DD + d);
        float4 o;
        o.x = zv.x + (cv.x - zv.x);
        o.y = zv.y + (cv.y - zv.y);
        o.z = zv.z + (cv.z - zv.z);
        o.w = zv.w + (cv.w - zv.w);
        ((float4*)out_code)[idx] = o;
        float dx = zv.x - cv.x, dy = zv.y - cv.y;
        float dz = zv.z - cv.z, dw = zv.w - cv.w;
        part += dx * dx + dy * dy + dz * dz + dw * dw;
    }
    #pragma unroll
    for (int o = 16; o > 0; o >>= 1) part += __shfl_xor_sync(0xffffffffu, part, o);
    __shared__ float sm[8];
    if ((threadIdx.x & 31) == 0) sm[threadIdx.x >> 5] = part;
    __syncthreads();
    if (threadIdx.x == 0) {
        float tot = 0.f;
        #pragma unroll
        for (int i = 0; i < 8; i++) tot += sm[i];
        g_losspart[blockIdx.x] = (double)tot;
    }
}

__global__ void finalize_kernel(float* __restrict__ out_loss) {
    __shared__ double sm[256];
    double s = 0.0;
    for (int i = threadIdx.x; i < 8192; i += 256) s += g_losspart[i];
    sm[threadIdx.x] = s;
    __syncthreads();
    for (int off = 128; off > 0; off >>= 1) {
        if (threadIdx.x < off) sm[threadIdx.x] += sm[threadIdx.x + off];
        __syncthreads();
    }
    if (threadIdx.x == 0) out_loss[0] = 0.25f * (float)(sm[0] / 33554432.0);
}

extern "C" void kernel_launch(void* const* d_in, const int* in_sizes, int n_in,
                              void* d_out, int out_size) {
    const float* z   = (const float*)d_in[0];
    const float* cb  = (const float*)d_in[1];
    const float* n_i = (const float*)d_in[2];
    const float* e_i = (const float*)d_in[3];
    float* out = (float*)d_out;

    halfnorm_kernel<<<KK, 256>>>(cb);                                   // #1
    cbconvert_kernel<<<KK, 256>>>(cb);                                  // #2
    argmin_tc_kernel<<<512, 256>>>(z, out + OFF_ENC, 0);                // #3 <- ncu
    argmin_tc_kernel<<<512, 256>>>(z, out + OFF_ENC, 65536);            // #4 <- ncu
    fixup_kernel<<<128, 256>>>(z, cb, out + OFF_ENC);                   // #5
    prefix_kernel<<<1, KK>>>();
    scatter_kernel<<<128, 256>>>();
    update_partial_kernel<<<KK * NSEG, 256>>>(z);
    update_reduce_kernel<<<KK, 256>>>(n_i, e_i, out + OFF_E, out + OFF_CB, out + OFF_N);
    gather_kernel<<<8192, 256>>>(z, cb, out);
    finalize_kernel<<<1, 256>>>(out + OFF_LOSS);
}